// round 14
// baseline (speedup 1.0000x reference)
#include <cuda_runtime.h>
#include <cuda_bf16.h>

#define N_NODES 100000
#define N_EDGES 1000000
#define DIM 64
#define EDIM 16
#define SCAN_BS 512
#define SCAN_NBLK ((N_NODES + SCAN_BS - 1) / SCAN_BS)   // 196
#define KEDGE 64
#define NGROUPS (N_EDGES / KEDGE)                       // 15625
#define GPB 16                                          // groups per block

__device__ int g_idx_is64;

// static scratch (no allocation)
__device__ int  g_cnt[N_NODES];
__device__ int  g_cur[N_NODES];
__device__ int  g_bsum[SCAN_NBLK];
__device__ int  g_bbase[SCAN_NBLK];
__device__ int4 g_sorted[N_EDGES];     // (src, eid, dst, 0) dst-sorted: 16 MB

// ---------------------------------------------------------------------------
// packed fp32x2 helpers
// ---------------------------------------------------------------------------
__device__ __forceinline__ unsigned long long f2_as_u64(float a, float b) {
    unsigned long long r;
    asm("mov.b64 %0, {%1, %2};" : "=l"(r) : "f"(a), "f"(b));
    return r;
}
__device__ __forceinline__ void u64_as_f2(unsigned long long v, float& a, float& b) {
    asm("mov.b64 {%0, %1}, %2;" : "=f"(a), "=f"(b) : "l"(v));
}
__device__ __forceinline__ void ffma2(unsigned long long& d,
                                      unsigned long long a, unsigned long long b) {
    asm("fma.rn.f32x2 %0, %1, %2, %0;" : "+l"(d) : "l"(a), "l"(b));
}

// ---------------------------------------------------------------------------
// Kernel 1: zero d_out + zero g_cnt + detect index dtype
// ---------------------------------------------------------------------------
__global__ void init_kernel(float4* __restrict__ out, int n4,
                            const unsigned int* __restrict__ w) {
    int i = blockIdx.x * 256 + threadIdx.x;
    if (i < n4) out[i] = make_float4(0.f, 0.f, 0.f, 0.f);
    if (i < N_NODES) g_cnt[i] = 0;
    if (blockIdx.x == 0) {
        __shared__ unsigned int nz[8];
        unsigned int v = w[2 * threadIdx.x + 1];
        unsigned int any = __ballot_sync(0xffffffffu, v != 0u);
        if ((threadIdx.x & 31) == 0) nz[threadIdx.x >> 5] = any;
        __syncthreads();
        if (threadIdx.x == 0) {
            unsigned int a = 0;
#pragma unroll
            for (int k = 0; k < 8; k++) a |= nz[k];
            g_idx_is64 = (a == 0u) ? 1 : 0;
        }
    }
}

// ---------------------------------------------------------------------------
// Kernel 2: histogram of dst
// ---------------------------------------------------------------------------
__global__ void hist_kernel(const void* __restrict__ ei_raw) {
    int e = blockIdx.x * 256 + threadIdx.x;
    if (e >= N_EDGES) return;
    int dst = g_idx_is64 ? (int)((const long long*)ei_raw)[N_EDGES + e]
                         : ((const int*)ei_raw)[N_EDGES + e];
    atomicAdd(&g_cnt[dst], 1);
}

// ---------------------------------------------------------------------------
// Kernels 3-5: exclusive scan of g_cnt -> g_cur
// ---------------------------------------------------------------------------
__global__ void scan1_kernel() {
    __shared__ int sh[SCAN_BS];
    int idx = blockIdx.x * SCAN_BS + threadIdx.x;
    sh[threadIdx.x] = (idx < N_NODES) ? g_cnt[idx] : 0;
    __syncthreads();
    for (int o = SCAN_BS / 2; o > 0; o >>= 1) {
        if (threadIdx.x < o) sh[threadIdx.x] += sh[threadIdx.x + o];
        __syncthreads();
    }
    if (threadIdx.x == 0) g_bsum[blockIdx.x] = sh[0];
}

__global__ void scan2_kernel() {
    __shared__ int sh[256];
    int t = threadIdx.x;
    int v = (t < SCAN_NBLK) ? g_bsum[t] : 0;
    sh[t] = v;
    __syncthreads();
    for (int o = 1; o < 256; o <<= 1) {
        int tmp = (t >= o) ? sh[t - o] : 0;
        __syncthreads();
        sh[t] += tmp;
        __syncthreads();
    }
    if (t < SCAN_NBLK) g_bbase[t] = sh[t] - v;
}

__global__ void scan3_kernel() {
    __shared__ int sh[SCAN_BS];
    int idx = blockIdx.x * SCAN_BS + threadIdx.x;
    int v = (idx < N_NODES) ? g_cnt[idx] : 0;
    sh[threadIdx.x] = v;
    __syncthreads();
    for (int o = 1; o < SCAN_BS; o <<= 1) {
        int t = (threadIdx.x >= o) ? sh[threadIdx.x - o] : 0;
        __syncthreads();
        sh[threadIdx.x] += t;
        __syncthreads();
    }
    if (idx < N_NODES) g_cur[idx] = g_bbase[blockIdx.x] + sh[threadIdx.x] - v;
}

// ---------------------------------------------------------------------------
// Kernel 6: scatter (src, eid, dst) records into dst-sorted order
// ---------------------------------------------------------------------------
__global__ void build_kernel(const void* __restrict__ ei_raw) {
    int e = blockIdx.x * 256 + threadIdx.x;
    if (e >= N_EDGES) return;
    int src, dst;
    if (g_idx_is64) {
        const long long* ei = (const long long*)ei_raw;
        src = (int)__ldcs(&ei[e]);
        dst = (int)__ldcs(&ei[N_EDGES + e]);
    } else {
        const int* ei = (const int*)ei_raw;
        src = __ldcs(&ei[e]);
        dst = __ldcs(&ei[N_EDGES + e]);
    }
    int pos = atomicAdd(&g_cur[dst], 1);
    g_sorted[pos] = make_int4(src, e, dst, 0);
}

// ---------------------------------------------------------------------------
// Kernel 7: run-aggregating message+gather over sorted edges.
// 16 half-warp groups/block; group owns 64 consecutive sorted slots; lane
// owns 4 cols. Records preloaded to SMEM. Flush decision is WARP-UNIFORM
// (__any_sync over both groups): a group whose dst didn't change flushes its
// partial early and restarts -- correct under atomics, keeps the branch
// non-divergent so unrolled ea/x loads batch.
//   msg = relu(x[src] + ea @ We + be)
// ---------------------------------------------------------------------------
__global__ __launch_bounds__(256) void aggregate_kernel(
    const float4* __restrict__ x4,
    const float4* __restrict__ ea4,
    const float4* __restrict__ be4,
    const float4* __restrict__ We4,
    float* __restrict__ aggr)
{
    __shared__ float4 Wes[EDIM * 16];    // 4 KB
    __shared__ int4   rec[GPB * KEDGE];  // 16 KB

    int tid = threadIdx.x;
    for (int i = tid; i < EDIM * 16; i += 256) Wes[i] = We4[i];

    int blockBase = blockIdx.x * (GPB * KEDGE);
    for (int i = tid; i < GPB * KEDGE; i += 256) {
        int4 v = make_int4(0, 0, 0, 0);          // safe default for tail
        if (blockBase + i < N_EDGES) v = __ldcs(&g_sorted[blockBase + i]);
        rec[i] = v;
    }
    __syncthreads();

    int gloc = tid >> 4;                 // 0..15
    int l    = tid & 15;
    int g    = blockIdx.x * GPB + gloc;
    bool valid = (g < NGROUPS);          // whole group valid or whole fake

    const int4* R = &rec[gloc * KEDGE];
    ulonglong2 be2 = ((const ulonglong2*)be4)[l];

    int cur = R[0].z;
    float4 acc = make_float4(0.f, 0.f, 0.f, 0.f);

#pragma unroll 8
    for (int j = 0; j < KEDGE; j++) {
        int4 r = R[j];                   // LDS (no global chain)

        const float4* ear = ea4 + (size_t)r.y * 4;
        float4 A0 = __ldcs(ear + 0);
        float4 A1 = __ldcs(ear + 1);
        float4 A2 = __ldcs(ear + 2);
        float4 A3 = __ldcs(ear + 3);
        float4 xv = x4[(size_t)r.x * 16 + l];

        unsigned long long p0 = be2.x, p1 = be2.y;
#define STEP(k, a) { unsigned long long av = f2_as_u64((a), (a));              \
                     ulonglong2 wv = *(const ulonglong2*)&Wes[(k) * 16 + l];   \
                     ffma2(p0, av, wv.x); ffma2(p1, av, wv.y); }
        STEP(0,  A0.x) STEP(1,  A0.y) STEP(2,  A0.z) STEP(3,  A0.w)
        STEP(4,  A1.x) STEP(5,  A1.y) STEP(6,  A1.z) STEP(7,  A1.w)
        STEP(8,  A2.x) STEP(9,  A2.y) STEP(10, A2.z) STEP(11, A2.w)
        STEP(12, A3.x) STEP(13, A3.y) STEP(14, A3.z) STEP(15, A3.w)
#undef STEP
        float m0, m1, m2, m3;
        u64_as_f2(p0, m0, m1);
        u64_as_f2(p1, m2, m3);
        m0 = fmaxf(m0 + xv.x, 0.f);
        m1 = fmaxf(m1 + xv.y, 0.f);
        m2 = fmaxf(m2 + xv.z, 0.f);
        m3 = fmaxf(m3 + xv.w, 0.f);

        bool myChange = (r.z != cur);    // uniform within a group
        if (__any_sync(0xffffffffu, myChange)) {   // uniform across the WARP
            if (valid) {
                float* p = aggr + (size_t)cur * DIM + l * 4;
                asm volatile("red.global.add.v4.f32 [%0], {%1,%2,%3,%4};"
                             :: "l"(p), "f"(acc.x), "f"(acc.y), "f"(acc.z), "f"(acc.w)
                             : "memory");
            }
            cur = r.z;
            acc = make_float4(m0, m1, m2, m3);
        } else {
            acc.x += m0; acc.y += m1; acc.z += m2; acc.w += m3;
        }
    }
    if (valid) {
        float* p = aggr + (size_t)cur * DIM + l * 4;
        asm volatile("red.global.add.v4.f32 [%0], {%1,%2,%3,%4};"
                     :: "l"(p), "f"(acc.x), "f"(acc.y), "f"(acc.z), "f"(acc.w)
                     : "memory");
    }
}

// ---------------------------------------------------------------------------
// Kernel 8: node epilogue. 8 nodes/warp, packed f32x2 MLP + LN + ReLU,
// 16B h-reads (R10 version).
// ---------------------------------------------------------------------------
#define NPW 8
__global__ __launch_bounds__(256, 4) void node_kernel(
    const float2* __restrict__ x,
    const float* __restrict__ W1,
    const float* __restrict__ b1,
    const float* __restrict__ W2,
    const float* __restrict__ b2,
    const float* __restrict__ gamma,
    const float* __restrict__ beta,
    float2* __restrict__ out)
{
    __shared__ unsigned long long W1p[32 * 64];
    __shared__ unsigned long long W2p[32 * 64];
    __shared__ float hs[8][NPW * DIM];

    int tid = threadIdx.x;
    for (int i = tid; i < 32 * 64; i += 256) {
        int k2 = i >> 6, c = i & 63;
        W1p[i] = f2_as_u64(W1[(2 * k2) * 64 + c], W1[(2 * k2 + 1) * 64 + c]);
        W2p[i] = f2_as_u64(W2[(2 * k2) * 64 + c], W2[(2 * k2 + 1) * 64 + c]);
    }
    __syncthreads();

    int w = tid >> 5, lane = tid & 31;
    int base = (blockIdx.x * 8 + w) * NPW;
    if (base >= N_NODES) return;
    float* h = hs[w];

#pragma unroll
    for (int n = 0; n < NPW; n++) {
        int node = base + n;
        if (node < N_NODES) {
            float2 xv = x[(size_t)node * 32 + lane];
            float2 av = out[(size_t)node * 32 + lane];
            *(float2*)&h[n * DIM + 2 * lane] = make_float2(xv.x + av.x, xv.y + av.y);
        }
    }
    __syncwarp();

    unsigned long long accA[NPW], accB[NPW];

    {
        float bA = b1[2 * lane], bB = b1[2 * lane + 1];
#pragma unroll
        for (int n = 0; n < NPW; n++) {
            accA[n] = f2_as_u64(bA, 0.f);
            accB[n] = f2_as_u64(bB, 0.f);
        }
    }
#pragma unroll
    for (int k4 = 0; k4 < 16; k4++) {
        ulonglong2 wpa = *(const ulonglong2*)&W1p[(2 * k4) * 64 + 2 * lane];
        ulonglong2 wpb = *(const ulonglong2*)&W1p[(2 * k4 + 1) * 64 + 2 * lane];
#pragma unroll
        for (int n = 0; n < NPW; n++) {
            ulonglong2 hh = *(const ulonglong2*)&h[n * DIM + 4 * k4];
            ffma2(accA[n], hh.x, wpa.x);
            ffma2(accB[n], hh.x, wpa.y);
            ffma2(accA[n], hh.y, wpb.x);
            ffma2(accB[n], hh.y, wpb.y);
        }
    }
    __syncwarp();
#pragma unroll
    for (int n = 0; n < NPW; n++) {
        float ax, ay, bx, by;
        u64_as_f2(accA[n], ax, ay);
        u64_as_f2(accB[n], bx, by);
        *(float2*)&h[n * DIM + 2 * lane] =
            make_float2(fmaxf(ax + ay, 0.f), fmaxf(bx + by, 0.f));
    }
    __syncwarp();

    {
        float bA = b2[2 * lane], bB = b2[2 * lane + 1];
#pragma unroll
        for (int n = 0; n < NPW; n++) {
            accA[n] = f2_as_u64(bA, 0.f);
            accB[n] = f2_as_u64(bB, 0.f);
        }
    }
#pragma unroll
    for (int k4 = 0; k4 < 16; k4++) {
        ulonglong2 wpa = *(const ulonglong2*)&W2p[(2 * k4) * 64 + 2 * lane];
        ulonglong2 wpb = *(const ulonglong2*)&W2p[(2 * k4 + 1) * 64 + 2 * lane];
#pragma unroll
        for (int n = 0; n < NPW; n++) {
            ulonglong2 hh = *(const ulonglong2*)&h[n * DIM + 4 * k4];
            ffma2(accA[n], hh.x, wpa.x);
            ffma2(accB[n], hh.x, wpa.y);
            ffma2(accA[n], hh.y, wpb.x);
            ffma2(accB[n], hh.y, wpb.y);
        }
    }

    float2 g  = make_float2(gamma[2 * lane], gamma[2 * lane + 1]);
    float2 bt = make_float2(beta[2 * lane],  beta[2 * lane + 1]);
    const float inv = 1.0f / DIM;

#pragma unroll
    for (int n = 0; n < NPW; n++) {
        float ax, ay, bx, by;
        u64_as_f2(accA[n], ax, ay);
        u64_as_f2(accB[n], bx, by);
        float v0 = ax + ay, v1 = bx + by;
        float s = v0 + v1, q = v0 * v0 + v1 * v1;
#pragma unroll
        for (int o = 16; o > 0; o >>= 1) {
            s += __shfl_xor_sync(0xffffffffu, s, o);
            q += __shfl_xor_sync(0xffffffffu, q, o);
        }
        float mu  = s * inv;
        float var = fmaxf(q * inv - mu * mu, 0.f);
        float r   = rsqrtf(var + 1e-5f);
        int node = base + n;
        if (node < N_NODES) {
            float2 o2;
            o2.x = fmaxf((v0 - mu) * r * g.x + bt.x, 0.f);
            o2.y = fmaxf((v1 - mu) * r * g.y + bt.y, 0.f);
            out[(size_t)node * 32 + lane] = o2;
        }
    }
}

// ---------------------------------------------------------------------------
// Launch
// ---------------------------------------------------------------------------
extern "C" void kernel_launch(void* const* d_in, const int* in_sizes, int n_in,
                              void* d_out, int out_size) {
    const float* x     = (const float*)d_in[0];
    const void*  ei    = d_in[1];
    const float* ea    = (const float*)d_in[2];
    const float* We    = (const float*)d_in[3];
    const float* be    = (const float*)d_in[4];
    const float* W1    = (const float*)d_in[5];
    const float* b1    = (const float*)d_in[6];
    const float* W2    = (const float*)d_in[7];
    const float* b2    = (const float*)d_in[8];
    const float* gamma = (const float*)d_in[9];
    const float* beta  = (const float*)d_in[10];
    float* out = (float*)d_out;

    int n4 = N_NODES * DIM / 4;
    init_kernel<<<(n4 + 255) / 256, 256>>>((float4*)out, n4,
                                           (const unsigned int*)ei);
    hist_kernel<<<(N_EDGES + 255) / 256, 256>>>(ei);
    scan1_kernel<<<SCAN_NBLK, SCAN_BS>>>();
    scan2_kernel<<<1, 256>>>();
    scan3_kernel<<<SCAN_NBLK, SCAN_BS>>>();
    build_kernel<<<(N_EDGES + 255) / 256, 256>>>(ei);

    int agg_blocks = (NGROUPS + GPB - 1) / GPB;   // 977
    aggregate_kernel<<<agg_blocks, 256>>>((const float4*)x, (const float4*)ea,
                                          (const float4*)be, (const float4*)We,
                                          out);

    node_kernel<<<(N_NODES + 63) / 64, 256>>>((const float2*)x, W1, b1, W2, b2,
                                              gamma, beta, (float2*)out);
}

// round 16
// speedup vs baseline: 1.9144x; 1.9144x over previous
#include <cuda_runtime.h>
#include <cuda_bf16.h>

#define N_NODES 100000
#define N_EDGES 1000000
#define DIM 64
#define EDIM 16

// Flag: 1 if edge_index is int64, 0 if int32.
__device__ int g_idx_is64;

// ---------------------------------------------------------------------------
// packed fp32x2 helpers (Blackwell FFMA2)
// ---------------------------------------------------------------------------
__device__ __forceinline__ unsigned long long f2_as_u64(float a, float b) {
    unsigned long long r;
    asm("mov.b64 %0, {%1, %2};" : "=l"(r) : "f"(a), "f"(b));
    return r;
}
__device__ __forceinline__ void u64_as_f2(unsigned long long v, float& a, float& b) {
    asm("mov.b64 {%0, %1}, %2;" : "=f"(a), "=f"(b) : "l"(v));
}
__device__ __forceinline__ void ffma2(unsigned long long& d,
                                      unsigned long long a, unsigned long long b) {
    asm("fma.rn.f32x2 %0, %1, %2, %0;" : "+l"(d) : "l"(a), "l"(b));
}

// ---------------------------------------------------------------------------
// Kernel 1: zero accumulator (d_out) + detect index dtype (block 0)
// ---------------------------------------------------------------------------
__global__ void zero_detect_kernel(float4* __restrict__ out, int n4,
                                   const unsigned int* __restrict__ w) {
    int i = blockIdx.x * 256 + threadIdx.x;
    if (i < n4) out[i] = make_float4(0.f, 0.f, 0.f, 0.f);
    if (blockIdx.x == 0) {
        __shared__ unsigned int nz[8];
        unsigned int v = w[2 * threadIdx.x + 1];
        unsigned int any = __ballot_sync(0xffffffffu, v != 0u);
        if ((threadIdx.x & 31) == 0) nz[threadIdx.x >> 5] = any;
        __syncthreads();
        if (threadIdx.x == 0) {
            unsigned int a = 0;
#pragma unroll
            for (int k = 0; k < 8; k++) a |= nz[k];
            g_idx_is64 = (a == 0u) ? 1 : 0;
        }
    }
}

// ---------------------------------------------------------------------------
// Kernel 2: per-edge message + atomic scatter. 8 edges/warp, fully unrolled
// 3-phase pipeline: all idx+ea loads issued first (addresses sequential,
// known a priori), then all independent x-gathers, then compute + REDG.
// We entirely in registers (zero crossbar). Lane owns 4 cols; red.v4/edge.
//   msg = relu(x[src] + ea @ We + be);  aggr[dst] += msg
// ---------------------------------------------------------------------------
#define EPW 8                               // edges per warp
#define NIT (EPW / 2)                       // 4 two-edge iterations
#define EDGE_WARPS (N_EDGES / EPW)          // 125000
__global__ __launch_bounds__(256) void edge_kernel(
    const float4* __restrict__ x4,
    const void* __restrict__ ei_raw,
    const float* __restrict__ ea,
    const float4* __restrict__ be4,
    const float4* __restrict__ We4,
    float* __restrict__ aggr)
{
    int gw   = blockIdx.x * 8 + (threadIdx.x >> 5);
    int lane = threadIdx.x & 31;
    int half = lane >> 4, l = lane & 15;
    if (gw >= EDGE_WARPS) return;

    // We[k][4l..4l+3] in registers (two packed f32x2 per k)
    unsigned long long Wr0[EDIM], Wr1[EDIM];
#pragma unroll
    for (int k = 0; k < EDIM; k++) {
        ulonglong2 wv = ((const ulonglong2*)We4)[k * 16 + l];
        Wr0[k] = wv.x;
        Wr1[k] = wv.y;
    }
    ulonglong2 be2 = ((const ulonglong2*)be4)[l];

    int base = gw * EPW;
    const bool is64 = (g_idx_is64 != 0);
    const long long* ei64 = (const long long*)ei_raw;
    const int*       ei32 = (const int*)ei_raw;

    // ---- phase 1: all idx + ea loads (independent, addresses sequential) ---
    int   srcs[NIT], dsts[NIT];
    float eav[NIT];
#pragma unroll
    for (int i = 0; i < NIT; i++) {
        int e = base + 2 * i + half;
        if (is64) {
            srcs[i] = (int)__ldcs(&ei64[e]);
            dsts[i] = (int)__ldcs(&ei64[N_EDGES + e]);
        } else {
            srcs[i] = __ldcs(&ei32[e]);
            dsts[i] = __ldcs(&ei32[N_EDGES + e]);
        }
        eav[i] = __ldcs(&ea[(size_t)e * EDIM + l]);
    }

    // ---- phase 2: all x-gathers (independent once srcs land) --------------
    float4 xv[NIT];
#pragma unroll
    for (int i = 0; i < NIT; i++)
        xv[i] = x4[(size_t)srcs[i] * 16 + l];

    // ---- phase 3: compute + scatter ---------------------------------------
#pragma unroll
    for (int i = 0; i < NIT; i++) {
        unsigned long long p0 = be2.x, p1 = be2.y;
#pragma unroll
        for (int k = 0; k < EDIM; k++) {
            float a = __shfl_sync(0xffffffffu, eav[i], (half << 4) | k);
            unsigned long long av = f2_as_u64(a, a);
            ffma2(p0, av, Wr0[k]);
            ffma2(p1, av, Wr1[k]);
        }
        float m0, m1, m2, m3;
        u64_as_f2(p0, m0, m1);
        u64_as_f2(p1, m2, m3);
        m0 = fmaxf(m0 + xv[i].x, 0.f);
        m1 = fmaxf(m1 + xv[i].y, 0.f);
        m2 = fmaxf(m2 + xv[i].z, 0.f);
        m3 = fmaxf(m3 + xv[i].w, 0.f);

        float* p = aggr + (size_t)dsts[i] * DIM + l * 4;
        asm volatile("red.global.add.v4.f32 [%0], {%1,%2,%3,%4};"
                     :: "l"(p), "f"(m0), "f"(m1), "f"(m2), "f"(m3)
                     : "memory");
    }
}

// ---------------------------------------------------------------------------
// Kernel 3: node epilogue. 8 nodes/warp, packed f32x2 MLP + LN + ReLU,
// 16B h-reads (proven R10 version).
// ---------------------------------------------------------------------------
#define NPW 8
__global__ __launch_bounds__(256, 4) void node_kernel(
    const float2* __restrict__ x,
    const float* __restrict__ W1,
    const float* __restrict__ b1,
    const float* __restrict__ W2,
    const float* __restrict__ b2,
    const float* __restrict__ gamma,
    const float* __restrict__ beta,
    float2* __restrict__ out)     // holds aggr on entry; overwritten in place
{
    __shared__ unsigned long long W1p[32 * 64];   // 16 KB
    __shared__ unsigned long long W2p[32 * 64];   // 16 KB
    __shared__ float hs[8][NPW * DIM];            // 16 KB

    int tid = threadIdx.x;
    for (int i = tid; i < 32 * 64; i += 256) {
        int k2 = i >> 6, c = i & 63;
        W1p[i] = f2_as_u64(W1[(2 * k2) * 64 + c], W1[(2 * k2 + 1) * 64 + c]);
        W2p[i] = f2_as_u64(W2[(2 * k2) * 64 + c], W2[(2 * k2 + 1) * 64 + c]);
    }
    __syncthreads();

    int w = tid >> 5, lane = tid & 31;
    int base = (blockIdx.x * 8 + w) * NPW;
    if (base >= N_NODES) return;
    float* h = hs[w];

#pragma unroll
    for (int n = 0; n < NPW; n++) {
        int node = base + n;
        if (node < N_NODES) {
            float2 xv = x[(size_t)node * 32 + lane];
            float2 av = out[(size_t)node * 32 + lane];
            *(float2*)&h[n * DIM + 2 * lane] = make_float2(xv.x + av.x, xv.y + av.y);
        }
    }
    __syncwarp();

    unsigned long long accA[NPW], accB[NPW];

    // ---- layer 1 ----
    {
        float bA = b1[2 * lane], bB = b1[2 * lane + 1];
#pragma unroll
        for (int n = 0; n < NPW; n++) {
            accA[n] = f2_as_u64(bA, 0.f);
            accB[n] = f2_as_u64(bB, 0.f);
        }
    }
#pragma unroll
    for (int k4 = 0; k4 < 16; k4++) {
        ulonglong2 wpa = *(const ulonglong2*)&W1p[(2 * k4) * 64 + 2 * lane];
        ulonglong2 wpb = *(const ulonglong2*)&W1p[(2 * k4 + 1) * 64 + 2 * lane];
#pragma unroll
        for (int n = 0; n < NPW; n++) {
            ulonglong2 hh = *(const ulonglong2*)&h[n * DIM + 4 * k4];
            ffma2(accA[n], hh.x, wpa.x);
            ffma2(accB[n], hh.x, wpa.y);
            ffma2(accA[n], hh.y, wpb.x);
            ffma2(accB[n], hh.y, wpb.y);
        }
    }
    __syncwarp();
#pragma unroll
    for (int n = 0; n < NPW; n++) {
        float ax, ay, bx, by;
        u64_as_f2(accA[n], ax, ay);
        u64_as_f2(accB[n], bx, by);
        *(float2*)&h[n * DIM + 2 * lane] =
            make_float2(fmaxf(ax + ay, 0.f), fmaxf(bx + by, 0.f));
    }
    __syncwarp();

    // ---- layer 2 ----
    {
        float bA = b2[2 * lane], bB = b2[2 * lane + 1];
#pragma unroll
        for (int n = 0; n < NPW; n++) {
            accA[n] = f2_as_u64(bA, 0.f);
            accB[n] = f2_as_u64(bB, 0.f);
        }
    }
#pragma unroll
    for (int k4 = 0; k4 < 16; k4++) {
        ulonglong2 wpa = *(const ulonglong2*)&W2p[(2 * k4) * 64 + 2 * lane];
        ulonglong2 wpb = *(const ulonglong2*)&W2p[(2 * k4 + 1) * 64 + 2 * lane];
#pragma unroll
        for (int n = 0; n < NPW; n++) {
            ulonglong2 hh = *(const ulonglong2*)&h[n * DIM + 4 * k4];
            ffma2(accA[n], hh.x, wpa.x);
            ffma2(accB[n], hh.x, wpa.y);
            ffma2(accA[n], hh.y, wpb.x);
            ffma2(accB[n], hh.y, wpb.y);
        }
    }

    // ---- LayerNorm + ReLU ----
    float2 g  = make_float2(gamma[2 * lane], gamma[2 * lane + 1]);
    float2 bt = make_float2(beta[2 * lane],  beta[2 * lane + 1]);
    const float inv = 1.0f / DIM;

#pragma unroll
    for (int n = 0; n < NPW; n++) {
        float ax, ay, bx, by;
        u64_as_f2(accA[n], ax, ay);
        u64_as_f2(accB[n], bx, by);
        float v0 = ax + ay, v1 = bx + by;
        float s = v0 + v1, q = v0 * v0 + v1 * v1;
#pragma unroll
        for (int o = 16; o > 0; o >>= 1) {
            s += __shfl_xor_sync(0xffffffffu, s, o);
            q += __shfl_xor_sync(0xffffffffu, q, o);
        }
        float mu  = s * inv;
        float var = fmaxf(q * inv - mu * mu, 0.f);
        float r   = rsqrtf(var + 1e-5f);
        int node = base + n;
        if (node < N_NODES) {
            float2 o2;
            o2.x = fmaxf((v0 - mu) * r * g.x + bt.x, 0.f);
            o2.y = fmaxf((v1 - mu) * r * g.y + bt.y, 0.f);
            out[(size_t)node * 32 + lane] = o2;
        }
    }
}

// ---------------------------------------------------------------------------
// Launch
// ---------------------------------------------------------------------------
extern "C" void kernel_launch(void* const* d_in, const int* in_sizes, int n_in,
                              void* d_out, int out_size) {
    const float* x     = (const float*)d_in[0];
    const void*  ei    = d_in[1];
    const float* ea    = (const float*)d_in[2];
    const float* We    = (const float*)d_in[3];
    const float* be    = (const float*)d_in[4];
    const float* W1    = (const float*)d_in[5];
    const float* b1    = (const float*)d_in[6];
    const float* W2    = (const float*)d_in[7];
    const float* b2    = (const float*)d_in[8];
    const float* gamma = (const float*)d_in[9];
    const float* beta  = (const float*)d_in[10];
    float* out = (float*)d_out;

    // 1) zero accumulator + detect index dtype
    int n4 = N_NODES * DIM / 4;
    zero_detect_kernel<<<(n4 + 255) / 256, 256>>>((float4*)out, n4,
                                                  (const unsigned int*)ei);

    // 2) edge messages + atomic scatter: 8 edges/warp, 8 warps/block
    int eblocks = (EDGE_WARPS + 7) / 8;
    edge_kernel<<<eblocks, 256>>>((const float4*)x, ei, ea,
                                  (const float4*)be, (const float4*)We, out);

    // 3) node MLP + LayerNorm: 64 nodes/block
    node_kernel<<<(N_NODES + 63) / 64, 256>>>((const float2*)x, W1, b1, W2, b2,
                                              gamma, beta, (float2*)out);
}